// round 4
// baseline (speedup 1.0000x reference)
#include <cuda_runtime.h>

#define NTHREADS 256

typedef unsigned long long u64;

// ---- packed f32x2 helpers (sm_100+ paired-fp32 ops) ----
__device__ __forceinline__ u64 pk2(float lo, float hi){
    u64 r; asm("mov.b64 %0, {%1,%2};" : "=l"(r) : "f"(lo), "f"(hi)); return r;
}
__device__ __forceinline__ void up2(u64 v, float& lo, float& hi){
    asm("mov.b64 {%0,%1}, %2;" : "=f"(lo), "=f"(hi) : "l"(v));
}
__device__ __forceinline__ u64 sw2(u64 v){           // (lo,hi) -> (hi,lo)
    float a, b; up2(v, a, b); return pk2(b, a);
}
__device__ __forceinline__ u64 mul2(u64 a, u64 b){
    u64 d; asm("mul.rn.f32x2 %0, %1, %2;" : "=l"(d) : "l"(a), "l"(b)); return d;
}
__device__ __forceinline__ u64 add2(u64 a, u64 b){
    u64 d; asm("add.rn.f32x2 %0, %1, %2;" : "=l"(d) : "l"(a), "l"(b)); return d;
}
__device__ __forceinline__ u64 fma2(u64 a, u64 b, u64 c){
    u64 d; asm("fma.rn.f32x2 %0, %1, %2, %3;" : "=l"(d) : "l"(a), "l"(b), "l"(c)); return d;
}

__global__ void __launch_bounds__(NTHREADS)
qdqn_kernel(const float* __restrict__ x,
            const float* __restrict__ w,
            const float* __restrict__ Wm,
            const float* __restrict__ bias,
            float* __restrict__ out,
            int Btot)
{
    // ---- per-block weight prep: tau = tan(w/2), P_l = prod_q cos(w_lq/2) ----
    __shared__ float s_tau[20];
    __shared__ float s_c[20];
    __shared__ float s_P[5];
    int tx = threadIdx.x;
    if (tx < 20){
        float c, s;
        sincosf(0.5f * w[tx], &s, &c);      // precise path: weights can sit near pi/2
        s_c[tx] = c;
        s_tau[tx] = __fdividef(s, c);
    }
    __syncthreads();
    if (tx < 5){
        s_P[tx] = s_c[4*tx] * s_c[4*tx+1] * s_c[4*tx+2] * s_c[4*tx+3];
    }
    __syncthreads();

    int tid = blockIdx.x * NTHREADS + tx;
    if (tid >= Btot) return;

    // ---- embedding half-angles: tangent form t_q, cosine product G ----
    float4 xv = reinterpret_cast<const float4*>(x)[tid];
    float xs[4] = {xv.x, xv.y, xv.z, xv.w};
    const float invb[4] = {1.0f/4.8f, 0.25f, 1.0f/0.418f, 0.25f};
    float t[4];
    float G = 1.0f;
    #pragma unroll
    for (int q = 0; q < 4; q++){
        float xn = xs[q] * invb[q];
        xn = fminf(fmaxf(xn, -1.0f), 1.0f);
        float S, C;
        __sincosf(xn * 1.57079632679f, &S, &C);
        float Cc = copysignf(fmaxf(fabsf(C), 1e-6f), C);   // guard tan blowup at the clip boundary
        t[q] = __fdividef(S, Cc);
        G *= Cc;
    }

    // ---- init: layer-0 RY product state (tangent rep) + layer-0 RX on qubit 0 folded ----
    float A[16];
    A[0]  = 1.0f;   A[8]  = t[0];
    A[4]  = t[1];   A[12] = t[0]*t[1];
    A[2]  = t[2];   A[10] = A[8]*t[2];  A[6] = A[4]*t[2];  A[14] = A[12]*t[2];
    A[1]  = t[3];   A[9]  = A[8]*t[3];  A[5] = A[4]*t[3];  A[13] = A[12]*t[3];
    A[3]  = A[2]*t[3]; A[11] = A[10]*t[3]; A[7] = A[6]*t[3]; A[15] = A[14]*t[3];

    u64 p[16];
    {
        float tau0 = s_tau[0];
        #pragma unroll
        for (int i = 0; i < 8; i++){
            int j = i | 8;
            p[i] = pk2(A[i], -tau0 * A[j]);   // a' = (re, -tau*partner_re): RX_q0 on real state
            p[j] = pk2(A[j], -tau0 * A[i]);
        }
    }

    const u64 NEG1 = pk2(-1.0f, -1.0f);

    // ---- layer 0 remainder: RX q1..q3, CNOT ring, rescale ----
    #pragma unroll
    for (int q = 1; q < 4; q++){
        const int m = 8 >> q;
        float tv = s_tau[q];
        u64 tau2 = pk2(tv, -tv);
        #pragma unroll
        for (int i = 0; i < 16; i++){
            if (i & m) continue;
            int j = i | m;
            u64 a = p[i], b = p[j];
            p[i] = fma2(tau2, sw2(b), a);     // a' = a - i*tau*b
            p[j] = fma2(tau2, sw2(a), b);
        }
    }
    #pragma unroll
    for (int q = 0; q < 4; q++){
        const int mc = 8 >> q, mt = 8 >> ((q + 1) & 3);
        #pragma unroll
        for (int i = 0; i < 16; i++){
            if ((i & mc) && !(i & mt)){
                u64 tmp = p[i]; p[i] = p[i | mt]; p[i | mt] = tmp;
            }
        }
    }
    {
        float R = G * s_P[0];
        u64 R2 = pk2(R, R);
        #pragma unroll
        for (int i = 0; i < 16; i++) p[i] = mul2(R2, p[i]);
    }

    // ---- layers 1..4: uniform body, NOT unrolled (keeps hot loop in L0 I$) ----
    #pragma unroll 1
    for (int l = 1; l < 5; l++){
        // RY re-uploading (tangent form, real coefficients)
        #pragma unroll
        for (int q = 0; q < 4; q++){
            const int m = 8 >> q;
            u64 nt2 = pk2(-t[q], -t[q]);
            u64 pt2 = pk2( t[q],  t[q]);
            #pragma unroll
            for (int i = 0; i < 16; i++){
                if (i & m) continue;
                int j = i | m;
                u64 a = p[i], b = p[j];
                p[i] = fma2(nt2, b, a);       // a - t*b
                p[j] = fma2(pt2, a, b);       // t*a + b
            }
        }
        // RX entangler (tangent form, -i*tau off-diagonal)
        #pragma unroll
        for (int q = 0; q < 4; q++){
            const int m = 8 >> q;
            float tv = s_tau[l*4 + q];
            u64 tau2 = pk2(tv, -tv);
            #pragma unroll
            for (int i = 0; i < 16; i++){
                if (i & m) continue;
                int j = i | m;
                u64 a = p[i], b = p[j];
                p[i] = fma2(tau2, sw2(b), a);
                p[j] = fma2(tau2, sw2(a), b);
            }
        }
        // CNOT ring: compile-time register permutation
        #pragma unroll
        for (int q = 0; q < 4; q++){
            const int mc = 8 >> q, mt = 8 >> ((q + 1) & 3);
            #pragma unroll
            for (int i = 0; i < 16; i++){
                if ((i & mc) && !(i & mt)){
                    u64 tmp = p[i]; p[i] = p[i | mt]; p[i | mt] = tmp;
                }
            }
        }
        // deferred cosine rescale (restores unit norm each layer)
        float R = G * s_P[l];
        u64 R2 = pk2(R, R);
        #pragma unroll
        for (int i = 0; i < 16; i++) p[i] = mul2(R2, p[i]);
    }

    // ---- probabilities (packed) and Walsh partial tree for <Z_q> ----
    u64 pr[16];
    #pragma unroll
    for (int i = 0; i < 16; i++) pr[i] = mul2(p[i], p[i]);   // (re^2, im^2)

    // stage qubit3 (mask 1)
    u64 s3[8];
    u64 e3v = fma2(NEG1, pr[1], pr[0]);
    s3[0] = add2(pr[0], pr[1]);
    #pragma unroll
    for (int k = 1; k < 8; k++){
        e3v = add2(e3v, fma2(NEG1, pr[2*k+1], pr[2*k]));
        s3[k] = add2(pr[2*k], pr[2*k+1]);
    }
    // stage qubit2 (mask 2)
    u64 s2v[4];
    u64 e2v = fma2(NEG1, s3[1], s3[0]);
    s2v[0] = add2(s3[0], s3[1]);
    #pragma unroll
    for (int k = 1; k < 4; k++){
        e2v = add2(e2v, fma2(NEG1, s3[2*k+1], s3[2*k]));
        s2v[k] = add2(s3[2*k], s3[2*k+1]);
    }
    // stage qubit1 (mask 4)
    u64 e1v = add2(fma2(NEG1, s2v[1], s2v[0]), fma2(NEG1, s2v[3], s2v[2]));
    u64 s1a = add2(s2v[0], s2v[1]);
    u64 s1b = add2(s2v[2], s2v[3]);
    // stage qubit0 (mask 8)
    u64 e0v = fma2(NEG1, s1b, s1a);

    float e[4], lo, hi;
    up2(e0v, lo, hi); e[0] = lo + hi;
    up2(e1v, lo, hi); e[1] = lo + hi;
    up2(e2v, lo, hi); e[2] = lo + hi;
    up2(e3v, lo, hi); e[3] = lo + hi;

    // ---- linear head ----
    float o0 = __ldg(bias + 0), o1 = __ldg(bias + 1);
    #pragma unroll
    for (int q = 0; q < 4; q++){
        o0 = fmaf(__ldg(Wm + q),     e[q], o0);
        o1 = fmaf(__ldg(Wm + 4 + q), e[q], o1);
    }
    reinterpret_cast<float2*>(out)[tid] = make_float2(o0, o1);
}

extern "C" void kernel_launch(void* const* d_in, const int* in_sizes, int n_in,
                              void* d_out, int out_size)
{
    const float* x  = (const float*)d_in[0];   // (B,4)
    const float* w  = (const float*)d_in[1];   // (5,4)
    const float* Wm = (const float*)d_in[2];   // (2,4)
    const float* b  = (const float*)d_in[3];   // (2,)
    int Btot = in_sizes[0] / 4;
    float* out = (float*)d_out;

    qdqn_kernel<<<(Btot + NTHREADS - 1) / NTHREADS, NTHREADS>>>(x, w, Wm, b, out, Btot);
}

// round 6
// speedup vs baseline: 1.4902x; 1.4902x over previous
#include <cuda_runtime.h>

#define NTHREADS 256

typedef unsigned long long u64;

// ---- packed f32x2 helpers (sm_100+ paired-fp32 ops) ----
__device__ __forceinline__ u64 pk2(float lo, float hi){
    u64 r; asm("mov.b64 %0, {%1,%2};" : "=l"(r) : "f"(lo), "f"(hi)); return r;
}
__device__ __forceinline__ void up2(u64 v, float& lo, float& hi){
    asm("mov.b64 {%0,%1}, %2;" : "=f"(lo), "=f"(hi) : "l"(v));
}
__device__ __forceinline__ u64 sw2(u64 v){           // (lo,hi) -> (hi,lo)
    float a, b; up2(v, a, b); return pk2(b, a);
}
__device__ __forceinline__ u64 mul2(u64 a, u64 b){
    u64 d; asm("mul.rn.f32x2 %0, %1, %2;" : "=l"(d) : "l"(a), "l"(b)); return d;
}
__device__ __forceinline__ u64 add2(u64 a, u64 b){
    u64 d; asm("add.rn.f32x2 %0, %1, %2;" : "=l"(d) : "l"(a), "l"(b)); return d;
}
__device__ __forceinline__ u64 fma2(u64 a, u64 b, u64 c){
    u64 d; asm("fma.rn.f32x2 %0, %1, %2, %3;" : "=l"(d) : "l"(a), "l"(b), "l"(c)); return d;
}

__global__ void __launch_bounds__(NTHREADS)
qdqn_kernel(const float* __restrict__ x,
            const float* __restrict__ w,
            const float* __restrict__ Wm,
            const float* __restrict__ bias,
            float* __restrict__ out,
            int Btot)
{
    // ---- per-block weight prep: tau = tan(w/2), P_l = prod_q cos(w_lq/2) ----
    __shared__ float s_tau[20];
    __shared__ float s_c[20];
    __shared__ float s_P[5];
    int tx = threadIdx.x;
    if (tx < 20){
        float c, s;
        sincosf(0.5f * w[tx], &s, &c);               // precise path (cost irrelevant: 20 threads)
        c = copysignf(fmaxf(fabsf(c), 1e-6f), c);    // guard w/2 ~ pi/2
        s_c[tx] = c;
        s_tau[tx] = __fdividef(s, c);
    }
    __syncthreads();
    if (tx < 5){
        s_P[tx] = s_c[4*tx] * s_c[4*tx+1] * s_c[4*tx+2] * s_c[4*tx+3];
    }
    __syncthreads();

    int tid = blockIdx.x * NTHREADS + tx;
    if (tid >= Btot) return;

    // ---- embedding half-angles: tangent form t_q, cosine product G ----
    float4 xv = reinterpret_cast<const float4*>(x)[tid];
    float xs[4] = {xv.x, xv.y, xv.z, xv.w};
    const float invb[4] = {1.0f/4.8f, 0.25f, 1.0f/0.418f, 0.25f};
    float t[4];
    float G = 1.0f;
    #pragma unroll
    for (int q = 0; q < 4; q++){
        float xn = xs[q] * invb[q];
        xn = fminf(fmaxf(xn, -1.0f), 1.0f);
        float S, C;
        __sincosf(xn * 1.57079632679f, &S, &C);
        float Cc = copysignf(fmaxf(fabsf(C), 1e-6f), C);   // guard tan blowup at the clip boundary
        t[q] = __fdividef(S, Cc);
        G *= Cc;
    }

    // ---- init: layer-0 RY product state (tangent rep) + layer-0 RX on qubit 0 folded ----
    float A[16];
    A[0]  = 1.0f;   A[8]  = t[0];
    A[4]  = t[1];   A[12] = t[0]*t[1];
    A[2]  = t[2];   A[10] = A[8]*t[2];  A[6] = A[4]*t[2];  A[14] = A[12]*t[2];
    A[1]  = t[3];   A[9]  = A[8]*t[3];  A[5] = A[4]*t[3];  A[13] = A[12]*t[3];
    A[3]  = A[2]*t[3]; A[11] = A[10]*t[3]; A[7] = A[6]*t[3]; A[15] = A[14]*t[3];

    u64 p[16];
    {
        float tau0 = s_tau[0];
        #pragma unroll
        for (int i = 0; i < 8; i++){
            int j = i | 8;
            p[i] = pk2(A[i], -tau0 * A[j]);   // RX_q0 applied to the (real) product state
            p[j] = pk2(A[j], -tau0 * A[i]);
        }
    }

    const u64 NEG1 = pk2(-1.0f, -1.0f);

    // ---- layer 0 remainder: RX q1..q3, CNOT ring, rescale ----
    #pragma unroll
    for (int q = 1; q < 4; q++){
        const int m = 8 >> q;
        float tv = s_tau[q];
        u64 tau2 = pk2(tv, -tv);
        #pragma unroll
        for (int i = 0; i < 16; i++){
            if (i & m) continue;
            int j = i | m;
            u64 a = p[i], b = p[j];
            p[i] = fma2(tau2, sw2(b), a);     // a' = a - i*tau*b
            p[j] = fma2(tau2, sw2(a), b);
        }
    }
    #pragma unroll
    for (int q = 0; q < 4; q++){
        const int mc = 8 >> q, mt = 8 >> ((q + 1) & 3);
        #pragma unroll
        for (int i = 0; i < 16; i++){
            if ((i & mc) && !(i & mt)){
                u64 tmp = p[i]; p[i] = p[i | mt]; p[i | mt] = tmp;
            }
        }
    }
    {
        float R = G * s_P[0];
        u64 R2 = pk2(R, R);
        #pragma unroll
        for (int i = 0; i < 16; i++) p[i] = mul2(R2, p[i]);
    }

    // ---- layers 1..4: FULLY unrolled (CNOTs become register renaming) ----
    #pragma unroll
    for (int l = 1; l < 5; l++){
        // RY re-uploading (tangent form, real coefficients): 1 fma2 per amplitude
        #pragma unroll
        for (int q = 0; q < 4; q++){
            const int m = 8 >> q;
            u64 nt2 = pk2(-t[q], -t[q]);
            u64 pt2 = pk2( t[q],  t[q]);
            #pragma unroll
            for (int i = 0; i < 16; i++){
                if (i & m) continue;
                int j = i | m;
                u64 a = p[i], b = p[j];
                p[i] = fma2(nt2, b, a);       // a - t*b
                p[j] = fma2(pt2, a, b);       // t*a + b
            }
        }
        // RX entangler (tangent form, -i*tau off-diagonal)
        #pragma unroll
        for (int q = 0; q < 4; q++){
            const int m = 8 >> q;
            float tv = s_tau[l*4 + q];
            u64 tau2 = pk2(tv, -tv);
            #pragma unroll
            for (int i = 0; i < 16; i++){
                if (i & m) continue;
                int j = i | m;
                u64 a = p[i], b = p[j];
                p[i] = fma2(tau2, sw2(b), a);
                p[j] = fma2(tau2, sw2(a), b);
            }
        }
        // CNOT ring: compile-time register permutation (free when unrolled)
        #pragma unroll
        for (int q = 0; q < 4; q++){
            const int mc = 8 >> q, mt = 8 >> ((q + 1) & 3);
            #pragma unroll
            for (int i = 0; i < 16; i++){
                if ((i & mc) && !(i & mt)){
                    u64 tmp = p[i]; p[i] = p[i | mt]; p[i | mt] = tmp;
                }
            }
        }
        // deferred cosine rescale EVERY layer: restores unit norm so the final
        // squaring cannot overflow (multi-clip samples reach t-products ~1e18+)
        float R = G * s_P[l];
        u64 R2 = pk2(R, R);
        #pragma unroll
        for (int i = 0; i < 16; i++) p[i] = mul2(R2, p[i]);
    }

    // ---- probabilities (packed) and Walsh partial tree for <Z_q> ----
    u64 pr[16];
    #pragma unroll
    for (int i = 0; i < 16; i++) pr[i] = mul2(p[i], p[i]);   // (re^2, im^2)

    // stage qubit3 (mask 1)
    u64 s3[8];
    u64 e3v = fma2(NEG1, pr[1], pr[0]);
    s3[0] = add2(pr[0], pr[1]);
    #pragma unroll
    for (int k = 1; k < 8; k++){
        e3v = add2(e3v, fma2(NEG1, pr[2*k+1], pr[2*k]));
        s3[k] = add2(pr[2*k], pr[2*k+1]);
    }
    // stage qubit2 (mask 2)
    u64 s2v[4];
    u64 e2v = fma2(NEG1, s3[1], s3[0]);
    s2v[0] = add2(s3[0], s3[1]);
    #pragma unroll
    for (int k = 1; k < 4; k++){
        e2v = add2(e2v, fma2(NEG1, s3[2*k+1], s3[2*k]));
        s2v[k] = add2(s3[2*k], s3[2*k+1]);
    }
    // stage qubit1 (mask 4)
    u64 e1v = add2(fma2(NEG1, s2v[1], s2v[0]), fma2(NEG1, s2v[3], s2v[2]));
    u64 s1a = add2(s2v[0], s2v[1]);
    u64 s1b = add2(s2v[2], s2v[3]);
    // stage qubit0 (mask 8)
    u64 e0v = fma2(NEG1, s1b, s1a);

    float e[4], lo, hi;
    up2(e0v, lo, hi); e[0] = lo + hi;
    up2(e1v, lo, hi); e[1] = lo + hi;
    up2(e2v, lo, hi); e[2] = lo + hi;
    up2(e3v, lo, hi); e[3] = lo + hi;

    // ---- linear head ----
    float o0 = __ldg(bias + 0), o1 = __ldg(bias + 1);
    #pragma unroll
    for (int q = 0; q < 4; q++){
        o0 = fmaf(__ldg(Wm + q),     e[q], o0);
        o1 = fmaf(__ldg(Wm + 4 + q), e[q], o1);
    }
    reinterpret_cast<float2*>(out)[tid] = make_float2(o0, o1);
}

extern "C" void kernel_launch(void* const* d_in, const int* in_sizes, int n_in,
                              void* d_out, int out_size)
{
    const float* x  = (const float*)d_in[0];   // (B,4)
    const float* w  = (const float*)d_in[1];   // (5,4)
    const float* Wm = (const float*)d_in[2];   // (2,4)
    const float* b  = (const float*)d_in[3];   // (2,)
    int Btot = in_sizes[0] / 4;
    float* out = (float*)d_out;

    qdqn_kernel<<<(Btot + NTHREADS - 1) / NTHREADS, NTHREADS>>>(x, w, Wm, b, out, Btot);
}

// round 8
// speedup vs baseline: 1.9221x; 1.2898x over previous
#include <cuda_runtime.h>

#define NTHREADS 256

typedef unsigned long long u64;

// ---- packed f32x2 helpers (sm_100+ paired-fp32 ops) ----
__device__ __forceinline__ u64 pk2(float lo, float hi){
    u64 r; asm("mov.b64 %0, {%1,%2};" : "=l"(r) : "f"(lo), "f"(hi)); return r;
}
__device__ __forceinline__ void up2(u64 v, float& lo, float& hi){
    asm("mov.b64 {%0,%1}, %2;" : "=f"(lo), "=f"(hi) : "l"(v));
}
__device__ __forceinline__ u64 mul2(u64 a, u64 b){
    u64 d; asm("mul.rn.f32x2 %0, %1, %2;" : "=l"(d) : "l"(a), "l"(b)); return d;
}
__device__ __forceinline__ u64 add2(u64 a, u64 b){
    u64 d; asm("add.rn.f32x2 %0, %1, %2;" : "=l"(d) : "l"(a), "l"(b)); return d;
}
__device__ __forceinline__ u64 fma2(u64 a, u64 b, u64 c){
    u64 d; asm("fma.rn.f32x2 %0, %1, %2, %3;" : "=l"(d) : "l"(a), "l"(b), "l"(c)); return d;
}

__global__ void __launch_bounds__(NTHREADS)
qdqn_kernel(const float* __restrict__ x,
            const float* __restrict__ w,
            const float* __restrict__ Wm,
            const float* __restrict__ bias,
            float* __restrict__ out,
            int Btot)
{
    // ---- per-block weight prep: tau = tan(w/2), P_l = prod_q cos(w_lq/2) ----
    __shared__ float s_tau[20];
    __shared__ float s_c[20];
    __shared__ float s_P[5];
    int tx = threadIdx.x;
    if (tx < 20){
        float c, s;
        sincosf(0.5f * w[tx], &s, &c);
        c = copysignf(fmaxf(fabsf(c), 1e-6f), c);    // guard w/2 ~ pi/2
        s_c[tx] = c;
        s_tau[tx] = __fdividef(s, c);
    }
    __syncthreads();
    if (tx < 5){
        s_P[tx] = s_c[4*tx] * s_c[4*tx+1] * s_c[4*tx+2] * s_c[4*tx+3];
    }
    __syncthreads();

    int tid = blockIdx.x * NTHREADS + tx;
    int s0 = 2 * tid;
    if (s0 >= Btot) return;
    bool has2 = (s0 + 1) < Btot;
    int s1 = has2 ? (s0 + 1) : s0;

    // ---- embedding half-angles per sample: tangent form, cosine product ----
    float4 xv0 = reinterpret_cast<const float4*>(x)[s0];
    float4 xv1 = reinterpret_cast<const float4*>(x)[s1];
    float xa[4] = {xv0.x, xv0.y, xv0.z, xv0.w};
    float xb[4] = {xv1.x, xv1.y, xv1.z, xv1.w};
    const float invb[4] = {1.0f/4.8f, 0.25f, 1.0f/0.418f, 0.25f};
    float tA[4], tB[4], GA = 1.0f, GB = 1.0f;
    #pragma unroll
    for (int q = 0; q < 4; q++){
        float xn = fminf(fmaxf(xa[q] * invb[q], -1.0f), 1.0f);
        float S, C;
        __sincosf(xn * 1.57079632679f, &S, &C);
        float Cc = copysignf(fmaxf(fabsf(C), 1e-6f), C);
        tA[q] = __fdividef(S, Cc);  GA *= Cc;
        xn = fminf(fmaxf(xb[q] * invb[q], -1.0f), 1.0f);
        __sincosf(xn * 1.57079632679f, &S, &C);
        Cc = copysignf(fmaxf(fabsf(C), 1e-6f), C);
        tB[q] = __fdividef(S, Cc);  GB *= Cc;
    }
    u64 t2[4], nt2[4];
    #pragma unroll
    for (int q = 0; q < 4; q++){
        t2[q]  = pk2( tA[q],  tB[q]);
        nt2[q] = pk2(-tA[q], -tB[q]);
    }
    u64 G2 = pk2(GA, GB);

    // ---- state: RE/IM of each amplitude, lanes = (sample0, sample1) ----
    u64 RE[16], IM[16];
    {
        // layer-0 RY product state (tangent rep), per sample, then pack
        float A0[16], A1[16];
        A0[0]=1.0f;          A0[8]=tA[0];
        A0[4]=tA[1];         A0[12]=tA[0]*tA[1];
        A0[2]=tA[2]; A0[10]=A0[8]*tA[2]; A0[6]=A0[4]*tA[2]; A0[14]=A0[12]*tA[2];
        A0[1]=tA[3]; A0[9]=A0[8]*tA[3];  A0[5]=A0[4]*tA[3]; A0[13]=A0[12]*tA[3];
        A0[3]=A0[2]*tA[3]; A0[11]=A0[10]*tA[3]; A0[7]=A0[6]*tA[3]; A0[15]=A0[14]*tA[3];
        A1[0]=1.0f;          A1[8]=tB[0];
        A1[4]=tB[1];         A1[12]=tB[0]*tB[1];
        A1[2]=tB[2]; A1[10]=A1[8]*tB[2]; A1[6]=A1[4]*tB[2]; A1[14]=A1[12]*tB[2];
        A1[1]=tB[3]; A1[9]=A1[8]*tB[3];  A1[5]=A1[4]*tB[3]; A1[13]=A1[12]*tB[3];
        A1[3]=A1[2]*tB[3]; A1[11]=A1[10]*tB[3]; A1[7]=A1[6]*tB[3]; A1[15]=A1[14]*tB[3];
        #pragma unroll
        for (int i = 0; i < 16; i++) RE[i] = pk2(A0[i], A1[i]);
        // layer-0 RX on qubit 0 folded: IM[i] = -tau0 * RE[i^8]
        float tau0 = s_tau[0];
        u64 ntau0 = pk2(-tau0, -tau0);
        #pragma unroll
        for (int i = 0; i < 16; i++) IM[i] = mul2(ntau0, RE[i ^ 8]);
    }

    const u64 NEG1 = pk2(-1.0f, -1.0f);

    // ---- layer 0 remainder: RX q1..q3, CNOT ring, rescale ----
    #pragma unroll
    for (int q = 1; q < 4; q++){
        const int m = 8 >> q;
        float tv = s_tau[q];
        u64 tau2  = pk2( tv,  tv);
        u64 ntau2 = pk2(-tv, -tv);
        #pragma unroll
        for (int i = 0; i < 16; i++){
            if (i & m) continue;
            int j = i | m;
            u64 ra = RE[i], rb = RE[j], ia = IM[i], ib = IM[j];
            RE[i] = fma2(tau2,  ib, ra);   // re_a + tau*im_b
            IM[i] = fma2(ntau2, rb, ia);   // im_a - tau*re_b
            RE[j] = fma2(tau2,  ia, rb);
            IM[j] = fma2(ntau2, ra, ib);
        }
    }
    #pragma unroll
    for (int q = 0; q < 4; q++){
        const int mc = 8 >> q, mt = 8 >> ((q + 1) & 3);
        #pragma unroll
        for (int i = 0; i < 16; i++){
            if ((i & mc) && !(i & mt)){
                u64 tr = RE[i]; RE[i] = RE[i|mt]; RE[i|mt] = tr;
                u64 ti = IM[i]; IM[i] = IM[i|mt]; IM[i|mt] = ti;
            }
        }
    }
    {
        u64 R2 = mul2(G2, pk2(s_P[0], s_P[0]));
        #pragma unroll
        for (int i = 0; i < 16; i++){ RE[i] = mul2(R2, RE[i]); IM[i] = mul2(R2, IM[i]); }
    }

    // ---- layers 1..4: FULLY unrolled; all ops lane-uniform, zero swaps ----
    #pragma unroll
    for (int l = 1; l < 5; l++){
        // RY re-uploading (tangent form): real rotation on RE and IM alike
        #pragma unroll
        for (int q = 0; q < 4; q++){
            const int m = 8 >> q;
            #pragma unroll
            for (int i = 0; i < 16; i++){
                if (i & m) continue;
                int j = i | m;
                u64 ra = RE[i], rb = RE[j], ia = IM[i], ib = IM[j];
                RE[i] = fma2(nt2[q], rb, ra);   // a - t*b
                RE[j] = fma2(t2[q],  ra, rb);   // t*a + b
                IM[i] = fma2(nt2[q], ib, ia);
                IM[j] = fma2(t2[q],  ia, ib);
            }
        }
        // RX entangler: multiply-by-(-i tau) = register selection, no swap
        #pragma unroll
        for (int q = 0; q < 4; q++){
            const int m = 8 >> q;
            float tv = s_tau[l*4 + q];
            u64 tau2  = pk2( tv,  tv);
            u64 ntau2 = pk2(-tv, -tv);
            #pragma unroll
            for (int i = 0; i < 16; i++){
                if (i & m) continue;
                int j = i | m;
                u64 ra = RE[i], rb = RE[j], ia = IM[i], ib = IM[j];
                RE[i] = fma2(tau2,  ib, ra);
                IM[i] = fma2(ntau2, rb, ia);
                RE[j] = fma2(tau2,  ia, rb);
                IM[j] = fma2(ntau2, ra, ib);
            }
        }
        // CNOT ring: whole-register permutation (free when unrolled)
        #pragma unroll
        for (int q = 0; q < 4; q++){
            const int mc = 8 >> q, mt = 8 >> ((q + 1) & 3);
            #pragma unroll
            for (int i = 0; i < 16; i++){
                if ((i & mc) && !(i & mt)){
                    u64 tr = RE[i]; RE[i] = RE[i|mt]; RE[i|mt] = tr;
                    u64 ti = IM[i]; IM[i] = IM[i|mt]; IM[i|mt] = ti;
                }
            }
        }
        // per-layer rescale: restores unit norm (prevents overflow at squaring)
        u64 R2 = mul2(G2, pk2(s_P[l], s_P[l]));
        #pragma unroll
        for (int i = 0; i < 16; i++){ RE[i] = mul2(R2, RE[i]); IM[i] = mul2(R2, IM[i]); }
    }

    // ---- probabilities (lanes = samples) and Walsh tree for <Z_q> ----
    u64 PR[16];
    #pragma unroll
    for (int i = 0; i < 16; i++) PR[i] = fma2(IM[i], IM[i], mul2(RE[i], RE[i]));

    // stage qubit3 (mask 1)
    u64 s3[8];
    u64 e3v = fma2(NEG1, PR[1], PR[0]);
    s3[0] = add2(PR[0], PR[1]);
    #pragma unroll
    for (int k = 1; k < 8; k++){
        e3v = add2(e3v, fma2(NEG1, PR[2*k+1], PR[2*k]));
        s3[k] = add2(PR[2*k], PR[2*k+1]);
    }
    // stage qubit2 (mask 2)
    u64 s2v[4];
    u64 e2v = fma2(NEG1, s3[1], s3[0]);
    s2v[0] = add2(s3[0], s3[1]);
    #pragma unroll
    for (int k = 1; k < 4; k++){
        e2v = add2(e2v, fma2(NEG1, s3[2*k+1], s3[2*k]));
        s2v[k] = add2(s3[2*k], s3[2*k+1]);
    }
    // stage qubit1 (mask 4)
    u64 e1v = add2(fma2(NEG1, s2v[1], s2v[0]), fma2(NEG1, s2v[3], s2v[2]));
    u64 s1a = add2(s2v[0], s2v[1]);
    u64 s1b = add2(s2v[2], s2v[3]);
    // stage qubit0 (mask 8)
    u64 e0v = fma2(NEG1, s1b, s1a);

    // ---- linear head, packed over samples, then unpack and store ----
    float w00 = __ldg(Wm+0), w01 = __ldg(Wm+1), w02 = __ldg(Wm+2), w03 = __ldg(Wm+3);
    float w10 = __ldg(Wm+4), w11 = __ldg(Wm+5), w12 = __ldg(Wm+6), w13 = __ldg(Wm+7);
    float b0 = __ldg(bias+0), b1 = __ldg(bias+1);
    u64 o0v = fma2(pk2(w00,w00), e0v, pk2(b0,b0));
    o0v = fma2(pk2(w01,w01), e1v, o0v);
    o0v = fma2(pk2(w02,w02), e2v, o0v);
    o0v = fma2(pk2(w03,w03), e3v, o0v);
    u64 o1v = fma2(pk2(w10,w10), e0v, pk2(b1,b1));
    o1v = fma2(pk2(w11,w11), e1v, o1v);
    o1v = fma2(pk2(w12,w12), e2v, o1v);
    o1v = fma2(pk2(w13,w13), e3v, o1v);

    float o0a, o0b, o1a, o1b;
    up2(o0v, o0a, o0b);
    up2(o1v, o1a, o1b);
    if (has2){
        reinterpret_cast<float4*>(out)[tid] = make_float4(o0a, o1a, o0b, o1b);
    } else {
        reinterpret_cast<float2*>(out)[s0] = make_float2(o0a, o1a);
    }
}

extern "C" void kernel_launch(void* const* d_in, const int* in_sizes, int n_in,
                              void* d_out, int out_size)
{
    const float* x  = (const float*)d_in[0];   // (B,4)
    const float* w  = (const float*)d_in[1];   // (5,4)
    const float* Wm = (const float*)d_in[2];   // (2,4)
    const float* b  = (const float*)d_in[3];   // (2,)
    int Btot = in_sizes[0] / 4;
    float* out = (float*)d_out;

    int nthreads_total = (Btot + 1) / 2;       // 2 samples per thread
    int nblocks = (nthreads_total + NTHREADS - 1) / NTHREADS;
    qdqn_kernel<<<nblocks, NTHREADS>>>(x, w, Wm, b, out, Btot);
}